// round 13
// baseline (speedup 1.0000x reference)
#include <cuda_runtime.h>
#include <math.h>

#define T_LEN 1024
#define DX    32
#define DZ    64
#define DY    256
#define NCTA  128
#define NTHR  256
#define ALPHA 0.125f
#define TDX   (T_LEN * DX)

// Packed fp32x2 FMA (Blackwell sm_103a): d = a*b + c elementwise on 64-bit pairs.
__device__ __forceinline__ float2 ffma2(float2 a, float2 b, float2 c) {
    unsigned long long au = *reinterpret_cast<unsigned long long*>(&a);
    unsigned long long bu = *reinterpret_cast<unsigned long long*>(&b);
    unsigned long long cu = *reinterpret_cast<unsigned long long*>(&c);
    unsigned long long du;
    asm("fma.rn.f32x2 %0, %1, %2, %3;" : "=l"(du) : "l"(au), "l"(bu), "l"(cu));
    return *reinterpret_cast<float2*>(&du);
}

// ---- stage macros (expand in kernel scope; s = stream index 0..3) ----

// S1: hidden_s = relu(W2 . zf_s + h2). Thread: y-pair (t&~1), k-half kh.
// Loads: 2 addrs/warp on disjoint bank-quads (KHPAD=36) -> 1 wf.
// Combine: ONE payload-split shfl; lane kh finalizes y = t. Store 1 wf.
#define S1(s) { \
    float2 A0={0.f,0.f}, A1={0.f,0.f}, B0={0.f,0.f}, B1={0.f,0.f}; \
    _Pragma("unroll") \
    for (int j = 0; j < 8; ++j) { \
        float4 v = *reinterpret_cast<const float4*>(&szf[s][kb + 4*j]); \
        float2 lo = make_float2(v.x, v.y), hi = make_float2(v.z, v.w); \
        A0 = ffma2(w2a[2*j],   lo, A0);  A1 = ffma2(w2a[2*j+1], hi, A1); \
        B0 = ffma2(w2b[2*j],   lo, B0);  B1 = ffma2(w2b[2*j+1], hi, B1); \
    } \
    float s0_ = (A0.x + A0.y) + (A1.x + A1.y); \
    float s1_ = (B0.x + B0.y) + (B1.x + B1.y); \
    float snd = kh ? s0_ : s1_; \
    float kp  = kh ? s1_ : s0_; \
    float F   = kp + __shfl_xor_sync(0xffffffffu, snd, 1); \
    sh[s][t] = fmaxf(F + h2y, 0.0f); \
}

// S2: partials of W1 . hidden_s. Thread: z-pair zp (lane-linear), y-chunk c
// (warp-uniform -> broadcast loads). Store float2 lane-linear (2-wf min).
#define S2(s) { \
    float2 C0={0.f,0.f}, C1={0.f,0.f}, D0={0.f,0.f}, D1={0.f,0.f}; \
    _Pragma("unroll") \
    for (int j = 0; j < 8; ++j) { \
        float4 hv = *reinterpret_cast<const float4*>(&sh[s][32*c + 4*j]); \
        float2 lo = make_float2(hv.x, hv.y), hi = make_float2(hv.z, hv.w); \
        C0 = ffma2(w1a[2*j],   lo, C0);  C1 = ffma2(w1a[2*j+1], hi, C1); \
        D0 = ffma2(w1b[2*j],   lo, D0);  D1 = ffma2(w1b[2*j+1], hi, D1); \
    } \
    float2 pr; \
    pr.x = (C0.x + C0.y) + (C1.x + C1.y); \
    pr.y = (D0.x + D0.y) + (D1.x + D1.y); \
    *reinterpret_cast<float2*>(&sP[s][c][2*zp]) = pr; \
}

// S0(s, u): reduce sPart_s -> znew(u-1); output; TF with x(u); publish zf_s(u).
// Runs on t<64 (thread owns z = t). All loads 1 wf, publish 1 wf.
#define S0(s, u) if (t < 64) { \
    float sum = ((sP[s][0][t] + sP[s][1][t]) + (sP[s][2][t] + sP[s][3][t])) \
              + ((sP[s][4][t] + sP[s][5][t]) + (sP[s][6][t] + sP[s][7][t])); \
    float znew = fmaf(Az, zc[s], sum + h1z); \
    float zf; \
    if (t < DX) { \
        Ob[(s) * TDX + ((u) - 1) * DX + t] = znew; \
        zf = fmaf(ALPHA, xn[s], 0.875f * znew); \
        if ((u) + 1 < T_LEN) xn[s] = Xb[(s) * TDX + ((u) + 1) * DX + t]; \
    } else { \
        zf = znew; \
    } \
    zc[s] = zf; \
    szf[s][zsl] = zf; \
}

// epilogue: reduce + output only (step T-1), no publish
#define S0OUT(s) if (t < 64) { \
    float sum = ((sP[s][0][t] + sP[s][1][t]) + (sP[s][2][t] + sP[s][3][t])) \
              + ((sP[s][4][t] + sP[s][5][t]) + (sP[s][6][t] + sP[s][7][t])); \
    float znew = fmaf(Az, zc[s], sum + h1z); \
    if (t < DX) Ob[(s) * TDX + (T_LEN - 1) * DX + t] = znew; \
}

__global__ __launch_bounds__(NTHR, 1)
void plrnn_kernel(const float* __restrict__ X,
                  const float* __restrict__ A,
                  const float* __restrict__ W1,   // (dz, dy) row-major
                  const float* __restrict__ W2,   // (dy, dz) row-major
                  const float* __restrict__ h1,
                  const float* __restrict__ h2,
                  float* __restrict__ out)        // (B, T, dx)
{
    __shared__ float szf[4][72];     // [stream][36*(z>>5) + (z&31)] forced state
    __shared__ float sh [4][256];    // [stream][y] hidden
    __shared__ float sP [4][8][64];  // [stream][ychunk][z] GEMM2 partials

    const int t  = threadIdx.x;
    const int kh = t & 1;                       // S1: k-half; y-pair = t&~1
    const int kb = kh * 36;
    const int y0 = t & ~1;
    const int zp = t & 31;                      // S2: z-pair (lane-linear)
    const int c  = t >> 5;                      // S2: y-chunk (warp-uniform)
    const int zsl = (t < 32) ? t : (36 + (t & 31));   // S0 publish slot (t<64)

    // ---- weights in registers, natural (even,odd) float2 pairs ----
    float2 w2a[16], w2b[16], w1a[16], w1b[16];
#pragma unroll
    for (int p = 0; p < 16; ++p) {
        w2a[p] = *reinterpret_cast<const float2*>(&W2[(size_t)y0       * DZ + 32*kh + 2*p]);
        w2b[p] = *reinterpret_cast<const float2*>(&W2[(size_t)(y0 + 1) * DZ + 32*kh + 2*p]);
        w1a[p] = *reinterpret_cast<const float2*>(&W1[(size_t)(2*zp)     * DY + 32*c + 2*p]);
        w1b[p] = *reinterpret_cast<const float2*>(&W1[(size_t)(2*zp + 1) * DY + 32*c + 2*p]);
    }
    const float h2y = h2[t];
    const float Az  = (t < 64) ? A[t]  : 0.0f;
    const float h1z = (t < 64) ? h1[t] : 0.0f;

    const float* Xb = X   + (size_t)blockIdx.x * 4 * TDX;
    float*       Ob = out + (size_t)blockIdx.x * 4 * TDX;

    float zc[4] = {0.f, 0.f, 0.f, 0.f};        // zf(current) per stream (t<64)
    float xn[4] = {0.f, 0.f, 0.f, 0.f};        // prefetched x per stream (t<32)

    // ---- init: publish zf(0) for all streams (z0 = x(0) for z<dx, else 0;
    //      step-0 blend of x(0) with itself is x(0); inputs are NaN-free) ----
    if (t < 64) {
#pragma unroll
        for (int s = 0; s < 4; ++s) {
            float v = 0.0f;
            if (t < DX) {
                v = Xb[s * TDX + t];
                xn[s] = Xb[s * TDX + DX + t];   // x(1)
            }
            zc[s] = v;
            szf[s][zsl] = v;
        }
    }
    __syncthreads();

    // ---- pipeline fill ----
    S1(2);                                      // sh_2(0)
    __syncthreads();
    S1(1); S2(2);                               // peel r0 (m=0)
    __syncthreads();
    S0(2, 1); S1(0); S1(3); S2(1);              // peel r1 (m=0)
    __syncthreads();
    S0(1, 1); S2(0); S2(3); S1(2);              // peel r2 (m=0)
    __syncthreads();

    // ---- steady state: 3 phases per step, 2 GEMM chains per phase ----
    for (int m = 1; m < T_LEN; ++m) {
        S0(0, m); S0(3, m); S1(1); S2(2);       // r0
        __syncthreads();
        S0(2, m + 1); S1(0); S1(3); S2(1);      // r1
        __syncthreads();
        S0(1, m + 1); S2(0); S2(3); S1(2);      // r2
        __syncthreads();
    }

    // ---- drain: last outputs for streams 0 and 3 (step T-1) ----
    S0OUT(0);
    S0OUT(3);
}

extern "C" void kernel_launch(void* const* d_in, const int* in_sizes, int n_in,
                              void* d_out, int out_size)
{
    const float* X  = (const float*)d_in[0];   // (512, 1024, 32)
    const float* A  = (const float*)d_in[1];   // (64,)
    const float* W1 = (const float*)d_in[2];   // (64, 256)
    const float* W2 = (const float*)d_in[3];   // (256, 64)
    const float* h1 = (const float*)d_in[4];   // (64,)
    const float* h2 = (const float*)d_in[5];   // (256,)
    plrnn_kernel<<<NCTA, NTHR>>>(X, A, W1, W2, h1, h2, (float*)d_out);
}

// round 14
// speedup vs baseline: 1.1637x; 1.1637x over previous
#include <cuda_runtime.h>
#include <math.h>

#define T_LEN 1024
#define DX    32
#define DZ    64
#define DY    256
#define BB    4
#define NCTA  128
#define NTHR  256
#define ALPHA 0.125f
#define KHPAD 36                 // padded offset of the second k-half in szfB rows
#define PROW  68                 // sPart z-row pad: STS.128 2-wf min, reduce 1 wf

// Packed fp32x2 FMA (Blackwell sm_103a): d = a*b + c elementwise on 64-bit pairs.
__device__ __forceinline__ float2 ffma2(float2 a, float2 b, float2 c) {
    unsigned long long au = *reinterpret_cast<unsigned long long*>(&a);
    unsigned long long bu = *reinterpret_cast<unsigned long long*>(&b);
    unsigned long long cu = *reinterpret_cast<unsigned long long*>(&c);
    unsigned long long du;
    asm("fma.rn.f32x2 %0, %1, %2, %3;" : "=l"(du) : "l"(au), "l"(bu), "l"(cu));
    return *reinterpret_cast<float2*>(&du);
}

__global__ __launch_bounds__(NTHR, 1)
void plrnn_kernel(const float* __restrict__ X,
                  const float* __restrict__ A,
                  const float* __restrict__ W1,   // (dz, dy) row-major
                  const float* __restrict__ W2,   // (dy, dz) row-major
                  const float* __restrict__ h1,
                  const float* __restrict__ h2,
                  float* __restrict__ out)        // (B, T, dx)
{
    __shared__ float szfB[BB][2 * KHPAD];    // [b][36*(k>>5) + (k&31)] zf
    __shared__ float shB [BB][DY];           // [b][y] hidden
    __shared__ float sPart[16][BB][PROW];    // [ychunk][b][z(+pad)] partials

    const int t  = threadIdx.x;

    // state / reduce role
    const int z   = t & 63;
    const int b   = t >> 6;
    const int bg  = blockIdx.x * BB + b;
    const int zsl = (z >> 5) * KHPAD + (z & 31);   // padded szfB slot

    // GEMM1 role (R3-exact): 2 consecutive y, one k-half, all 4 batches
    const int q   = t >> 1;                  // 0..127
    const int y0  = 2 * q;
    const int kh  = t & 1;                   // k-half; partner = lane^1
    const int kb  = kh * KHPAD;

    // GEMM2 role (widened): 4 consecutive z, one 16-wide y chunk, all 4 batches
    const int zq  = t & 15;                  // z-quad id
    const int z4  = 4 * zq;                  // z base
    const int g16 = t >> 4;                  // y chunk 0..15 (2 per warp)

    // ---- weights in registers, natural (even,odd) float2 pairs (no dup) ----
    float2 w2a[16], w2b[16];                 // W2 rows y0/y0+1, this k-half
#pragma unroll
    for (int p = 0; p < 16; ++p) {
        w2a[p] = *reinterpret_cast<const float2*>(&W2[(size_t)y0 * DZ + 32 * kh + 2 * p]);
        w2b[p] = *reinterpret_cast<const float2*>(&W2[(size_t)(y0 + 1) * DZ + 32 * kh + 2 * p]);
    }
    float2 w1r[4][8];                        // W1 rows z4..z4+3, y in [16*g16, +16)
#pragma unroll
    for (int zi = 0; zi < 4; ++zi)
#pragma unroll
        for (int p = 0; p < 8; ++p)
            w1r[zi][p] = *reinterpret_cast<const float2*>(
                &W1[(size_t)(z4 + zi) * DY + 16 * g16 + 2 * p]);

    const float2 h2v = *reinterpret_cast<const float2*>(&h2[y0]);
    const float  Az  = A[z];
    const float  h1z = h1[z];

    const float* Xb = X   + (size_t)bg * T_LEN * DX;
    float*       Ob = out + (size_t)bg * T_LEN * DX;

    // ---- z0: first dx dims forced with alpha=1, rest zero (inputs NaN-free) ----
    float zcur = 0.0f, x_next = 0.0f;
    if (z < DX) {
        zcur   = Xb[z];
        x_next = zcur;                        // step-0 forcing reuses X[:,0]
    }

    for (int step = 0; step < T_LEN; ++step) {
        // ---- phase 0: teacher forcing, publish zf ----
        float zf;
        if (z < DX) {                         // warp-uniform branch
            zf = fmaf(ALPHA, x_next, (1.0f - ALPHA) * zcur);
            if (step + 1 < T_LEN)
                x_next = Xb[(size_t)(step + 1) * DX + z];
        } else {
            zf = zcur;
        }
        szfB[b][zsl] = zf;                    // 1 wf
        __syncthreads();                      // B1: zf ready

        // ---- GEMM1 (R3-exact): partial[y0/y1][bb] over this thread's 32 k ----
        {
            float2 a0[BB], a1[BB];
#pragma unroll
            for (int bb = 0; bb < BB; ++bb) { a0[bb] = make_float2(0.f, 0.f);
                                              a1[bb] = make_float2(0.f, 0.f); }
#pragma unroll
            for (int j = 0; j < 8; ++j) {
#pragma unroll
                for (int bb = 0; bb < BB; ++bb) {
                    float4 v = *reinterpret_cast<const float4*>(&szfB[bb][kb + 4 * j]);
                    float2 lo = make_float2(v.x, v.y), hi = make_float2(v.z, v.w);
                    a0[bb] = ffma2(w2a[2 * j],     lo, a0[bb]);
                    a0[bb] = ffma2(w2a[2 * j + 1], hi, a0[bb]);
                    a1[bb] = ffma2(w2b[2 * j],     lo, a1[bb]);
                    a1[bb] = ffma2(w2b[2 * j + 1], hi, a1[bb]);
                }
            }
            float s0[BB], s1[BB];
#pragma unroll
            for (int bb = 0; bb < BB; ++bb) {
                s0[bb] = a0[bb].x + a0[bb].y;
                s1[bb] = a1[bb].x + a1[bb].y;
                s0[bb] += __shfl_xor_sync(0xffffffffu, s0[bb], 1);
                s1[bb] += __shfl_xor_sync(0xffffffffu, s1[bb], 1);
            }
            int bs = kh * 2;                  // lane kh stores batches {2kh, 2kh+1}
#pragma unroll
            for (int u = 0; u < 2; ++u) {
                int bb = bs + u;
                float2 hv;
                hv.x = fmaxf(s0[bb] + h2v.x, 0.0f);
                hv.y = fmaxf(s1[bb] + h2v.y, 0.0f);
                *reinterpret_cast<float2*>(&shB[bb][y0]) = hv;   // 2-wf min
            }
        }
        __syncthreads();                      // B2: hidden ready

        // ---- GEMM2 (widened): 4z x 4b over 16-wide y chunk; ratio 8 fma2/load ----
        {
            float2 c[4][BB];                  // [zi][bb] (even-y, odd-y) partials
#pragma unroll
            for (int zi = 0; zi < 4; ++zi)
#pragma unroll
                for (int bb = 0; bb < BB; ++bb) c[zi][bb] = make_float2(0.f, 0.f);
#pragma unroll
            for (int yq = 0; yq < 4; ++yq) {
#pragma unroll
                for (int bb = 0; bb < BB; ++bb) {
                    // 2 addrs/warp (g16 halves), disjoint quads: 1 wf
                    float4 hv = *reinterpret_cast<const float4*>(&shB[bb][16 * g16 + 4 * yq]);
                    float2 lo = make_float2(hv.x, hv.y), hi = make_float2(hv.z, hv.w);
#pragma unroll
                    for (int zi = 0; zi < 4; ++zi) {
                        c[zi][bb] = ffma2(w1r[zi][2 * yq],     lo, c[zi][bb]);
                        c[zi][bb] = ffma2(w1r[zi][2 * yq + 1], hi, c[zi][bb]);
                    }
                }
            }
#pragma unroll
            for (int bb = 0; bb < BB; ++bb) {
                float4 pr;
                pr.x = c[0][bb].x + c[0][bb].y;
                pr.y = c[1][bb].x + c[1][bb].y;
                pr.z = c[2][bb].x + c[2][bb].y;
                pr.w = c[3][bb].x + c[3][bb].y;
                *reinterpret_cast<float4*>(&sPart[g16][bb][z4]) = pr;  // 2-wf min
            }
        }
        __syncthreads();                      // B3: partials ready

        // ---- reduce 16 chunks + state update + output ----
        {
            float s = 0.0f;
#pragma unroll
            for (int g = 0; g < 16; ++g) s += sPart[g][b][z];   // 1 wf each
            float znew = fmaf(Az, zf, s + h1z);
            zcur = znew;
            if (z < DX)
                Ob[(size_t)step * DX + z] = znew;   // coalesced
        }
    }
}

extern "C" void kernel_launch(void* const* d_in, const int* in_sizes, int n_in,
                              void* d_out, int out_size)
{
    const float* X  = (const float*)d_in[0];   // (512, 1024, 32)
    const float* A  = (const float*)d_in[1];   // (64,)
    const float* W1 = (const float*)d_in[2];   // (64, 256)
    const float* W2 = (const float*)d_in[3];   // (256, 64)
    const float* h1 = (const float*)d_in[4];   // (64,)
    const float* h2 = (const float*)d_in[5];   // (256,)
    plrnn_kernel<<<NCTA, NTHR>>>(X, A, W1, W2, h1, h2, (float*)d_out);
}

// round 15
// speedup vs baseline: 1.5597x; 1.3403x over previous
#include <cuda_runtime.h>
#include <math.h>

#define T_LEN 1024
#define DX    32
#define DZ    64
#define DY    256
#define BB    4
#define NCTA  128
#define NTHR  256
#define ALPHA 0.125f
#define KHPAD 36                 // padded offset of the second k-half in szfB rows

// Packed fp32x2 FMA (Blackwell sm_103a): d = a*b + c elementwise on 64-bit pairs.
__device__ __forceinline__ float2 ffma2(float2 a, float2 b, float2 c) {
    unsigned long long au = *reinterpret_cast<unsigned long long*>(&a);
    unsigned long long bu = *reinterpret_cast<unsigned long long*>(&b);
    unsigned long long cu = *reinterpret_cast<unsigned long long*>(&c);
    unsigned long long du;
    asm("fma.rn.f32x2 %0, %1, %2, %3;" : "=l"(du) : "l"(au), "l"(bu), "l"(cu));
    return *reinterpret_cast<float2*>(&du);
}

__global__ __launch_bounds__(NTHR, 1)
void plrnn_kernel(const float* __restrict__ X,
                  const float* __restrict__ A,
                  const float* __restrict__ W1,   // (dz, dy) row-major
                  const float* __restrict__ W2,   // (dy, dz) row-major
                  const float* __restrict__ h1,
                  const float* __restrict__ h2,
                  float* __restrict__ out)        // (B, T, dx)
{
    __shared__ float szfB[BB][2 * KHPAD];   // [b][k-half * 36 + k%32], padded halves
    __shared__ float shB [BB][DY];          // [b][y] hidden
    __shared__ float sPart[8][BB][DZ];      // [ygroup][b][z] partial sums

    const int t  = threadIdx.x;

    // state / reduce role
    const int z   = t & 63;
    const int b   = t >> 6;
    const int bg  = blockIdx.x * BB + b;
    const int zsl = (z >> 5) * KHPAD + (z & 31);   // padded szfB slot

    // GEMM1 role: 2 consecutive y, one k-half, all 4 batches; partner = lane^1
    const int q   = t >> 1;                  // 0..127
    const int y0  = 2 * q;
    const int kh  = t & 1;                   // k-half (0: k<32, 1: k>=32)
    const int kb  = kh * KHPAD;              // padded base in szfB row

    // GEMM2 role: 2 consecutive z, one 32-wide y group, all 4 batches
    const int zg0 = (t & 31) * 2;
    const int g8  = t >> 5;

    // ---- weights in registers, natural (even,odd) float2 pairs (no dup) ----
    float2 w2a[16], w2b[16];                 // W2 rows y0/y0+1, this thread's k-half
#pragma unroll
    for (int p = 0; p < 16; ++p) {
        w2a[p] = *reinterpret_cast<const float2*>(&W2[(size_t)y0 * DZ + 32 * kh + 2 * p]);
        w2b[p] = *reinterpret_cast<const float2*>(&W2[(size_t)(y0 + 1) * DZ + 32 * kh + 2 * p]);
    }
    float2 w1a[16], w1b[16];                 // W1 rows zg0/zg0+1, cols [32*g8, +32)
#pragma unroll
    for (int p = 0; p < 16; ++p) {
        w1a[p] = *reinterpret_cast<const float2*>(&W1[(size_t)zg0 * DY + 32 * g8 + 2 * p]);
        w1b[p] = *reinterpret_cast<const float2*>(&W1[(size_t)(zg0 + 1) * DY + 32 * g8 + 2 * p]);
    }
    const float2 h2v = *reinterpret_cast<const float2*>(&h2[y0]);
    const float  Az  = A[z];
    const float  h1z = h1[z];

    const float* Xb = X   + (size_t)bg * T_LEN * DX;
    float*       Ob = out + (size_t)bg * T_LEN * DX;

    // ---- z0: first dx dims forced with alpha=1, rest zero ----
    float zcur = 0.0f, x_next = 0.0f;
    if (z < DX) {
        float x0 = Xb[z];
        zcur   = (x0 != x0) ? 0.0f : x0;     // NaN -> keep 0
        x_next = x0;                          // step-0 forcing reuses X[:,0]
    }

    for (int step = 0; step < T_LEN; ++step) {
        // ---- phase 0: teacher forcing, publish zf ----
        float zf;
        if (z < DX) {
            float x = x_next;
            zf = (x != x) ? zcur : fmaf(ALPHA, x, (1.0f - ALPHA) * zcur);
        } else {
            zf = zcur;
        }
        szfB[b][zsl] = zf;
        if (z < DX && step + 1 < T_LEN)
            x_next = Xb[(size_t)(step + 1) * DX + z];   // prefetch for next iter
        __syncthreads();                                 // B1: zf ready

        // ---- GEMM1 (k-split): partial[y0/y1][bb] over this thread's 32 k ----
        float2 a0[BB], a1[BB];
#pragma unroll
        for (int bb = 0; bb < BB; ++bb) { a0[bb] = make_float2(0.f, 0.f);
                                          a1[bb] = make_float2(0.f, 0.f); }
#pragma unroll
        for (int j = 0; j < 8; ++j) {
#pragma unroll
            for (int bb = 0; bb < BB; ++bb) {
                float4 v = *reinterpret_cast<const float4*>(&szfB[bb][kb + 4 * j]);
                float2 lo = make_float2(v.x, v.y), hi = make_float2(v.z, v.w);
                a0[bb] = ffma2(w2a[2 * j],     lo, a0[bb]);
                a0[bb] = ffma2(w2a[2 * j + 1], hi, a0[bb]);
                a1[bb] = ffma2(w2b[2 * j],     lo, a1[bb]);
                a1[bb] = ffma2(w2b[2 * j + 1], hi, a1[bb]);
            }
        }
        // combine k-halves with partner lane (lane^1), relu, store 2 batches each
        {
            float s0[BB], s1[BB];
#pragma unroll
            for (int bb = 0; bb < BB; ++bb) {
                s0[bb] = a0[bb].x + a0[bb].y;
                s1[bb] = a1[bb].x + a1[bb].y;
                s0[bb] += __shfl_xor_sync(0xffffffffu, s0[bb], 1);
                s1[bb] += __shfl_xor_sync(0xffffffffu, s1[bb], 1);
            }
            // kh==0 stores batches 0,1; kh==1 stores batches 2,3
            int bs = kh * 2;
#pragma unroll
            for (int u = 0; u < 2; ++u) {
                int bb = bs + u;
                float2 hv;
                hv.x = fmaxf(s0[bb] + h2v.x, 0.0f);
                hv.y = fmaxf(s1[bb] + h2v.y, 0.0f);
                *reinterpret_cast<float2*>(&shB[bb][y0]) = hv;
            }
        }
        __syncthreads();                                 // B2: hidden ready

        // ---- GEMM2: part[g8][b][z] = W1[z, 32g8:+32] . hidden[32g8:+32, b] ----
        float2 c0[BB], c1[BB];
#pragma unroll
        for (int bb = 0; bb < BB; ++bb) { c0[bb] = make_float2(0.f, 0.f);
                                          c1[bb] = make_float2(0.f, 0.f); }
#pragma unroll
        for (int yq = 0; yq < 8; ++yq) {
#pragma unroll
            for (int bb = 0; bb < BB; ++bb) {
                float4 hv = *reinterpret_cast<const float4*>(&shB[bb][32 * g8 + 4 * yq]);
                float2 lo = make_float2(hv.x, hv.y), hi = make_float2(hv.z, hv.w);
                c0[bb] = ffma2(w1a[2 * yq],     lo, c0[bb]);
                c0[bb] = ffma2(w1a[2 * yq + 1], hi, c0[bb]);
                c1[bb] = ffma2(w1b[2 * yq],     lo, c1[bb]);
                c1[bb] = ffma2(w1b[2 * yq + 1], hi, c1[bb]);
            }
        }
#pragma unroll
        for (int bb = 0; bb < BB; ++bb) {
            float2 pr;
            pr.x = c0[bb].x + c0[bb].y;                  // z = zg0
            pr.y = c1[bb].x + c1[bb].y;                  // z = zg0+1
            *reinterpret_cast<float2*>(&sPart[g8][bb][zg0]) = pr;
        }
        __syncthreads();                                 // B3: partials ready

        // ---- reduce 8 groups + state update + output ----
        float s = 0.0f;
#pragma unroll
        for (int g = 0; g < 8; ++g) s += sPart[g][b][z];
        float znew = fmaf(Az, zf, s + h1z);
        zcur = znew;
        if (z < DX)
            Ob[(size_t)step * DX + z] = znew;            // coalesced
    }
}

extern "C" void kernel_launch(void* const* d_in, const int* in_sizes, int n_in,
                              void* d_out, int out_size)
{
    const float* X  = (const float*)d_in[0];   // (512, 1024, 32)
    const float* A  = (const float*)d_in[1];   // (64,)
    const float* W1 = (const float*)d_in[2];   // (64, 256)
    const float* W2 = (const float*)d_in[3];   // (256, 64)
    const float* h1 = (const float*)d_in[4];   // (64,)
    const float* h2 = (const float*)d_in[5];   // (256,)
    plrnn_kernel<<<NCTA, NTHR>>>(X, A, W1, W2, h1, h2, (float*)d_out);
}

// round 16
// speedup vs baseline: 1.5657x; 1.0039x over previous
#include <cuda_runtime.h>
#include <math.h>

#define T_LEN 1024
#define DX    32
#define DZ    64
#define DY    256
#define BB    4
#define NCTA  128
#define NTHR  256
#define ALPHA 0.125f
#define KHPAD 36                 // padded offset of the second k-half in szfB rows

// Packed fp32x2 FMA (Blackwell sm_103a): d = a*b + c elementwise on 64-bit pairs.
__device__ __forceinline__ float2 ffma2(float2 a, float2 b, float2 c) {
    unsigned long long au = *reinterpret_cast<unsigned long long*>(&a);
    unsigned long long bu = *reinterpret_cast<unsigned long long*>(&b);
    unsigned long long cu = *reinterpret_cast<unsigned long long*>(&c);
    unsigned long long du;
    asm("fma.rn.f32x2 %0, %1, %2, %3;" : "=l"(du) : "l"(au), "l"(bu), "l"(cu));
    return *reinterpret_cast<float2*>(&du);
}

__global__ __launch_bounds__(NTHR, 1)
void plrnn_kernel(const float* __restrict__ X,
                  const float* __restrict__ A,
                  const float* __restrict__ W1,   // (dz, dy) row-major
                  const float* __restrict__ W2,   // (dy, dz) row-major
                  const float* __restrict__ h1,
                  const float* __restrict__ h2,
                  float* __restrict__ out)        // (B, T, dx)
{
    __shared__ float szfB[BB][2 * KHPAD];   // [b][k-half * 36 + k%32], padded halves
    __shared__ float shB [BB][DY];          // [b][y] hidden
    __shared__ float sPart[8][BB][DZ];      // [ygroup][b][z] partial sums

    const int t  = threadIdx.x;

    // state / reduce role
    const int z   = t & 63;
    const int b   = t >> 6;
    const int bg  = blockIdx.x * BB + b;
    const int zsl = (z >> 5) * KHPAD + (z & 31);   // padded szfB slot

    // GEMM1 role: 2 consecutive y, one k-half, all 4 batches; partner = lane^1
    const int q   = t >> 1;                  // 0..127
    const int y0  = 2 * q;
    const int kh  = t & 1;                   // k-half (0: k<32, 1: k>=32)
    const int kb  = kh * KHPAD;              // padded base in szfB row

    // GEMM2 role: 2 consecutive z, one 32-wide y group, all 4 batches
    const int zg0 = (t & 31) * 2;
    const int g8  = t >> 5;

    // ---- weights in registers, natural (even,odd) float2 pairs (no dup) ----
    float2 w2a[16], w2b[16];                 // W2 rows y0/y0+1, this thread's k-half
#pragma unroll
    for (int p = 0; p < 16; ++p) {
        w2a[p] = *reinterpret_cast<const float2*>(&W2[(size_t)y0 * DZ + 32 * kh + 2 * p]);
        w2b[p] = *reinterpret_cast<const float2*>(&W2[(size_t)(y0 + 1) * DZ + 32 * kh + 2 * p]);
    }
    float2 w1a[16], w1b[16];                 // W1 rows zg0/zg0+1, cols [32*g8, +32)
#pragma unroll
    for (int p = 0; p < 16; ++p) {
        w1a[p] = *reinterpret_cast<const float2*>(&W1[(size_t)zg0 * DY + 32 * g8 + 2 * p]);
        w1b[p] = *reinterpret_cast<const float2*>(&W1[(size_t)(zg0 + 1) * DY + 32 * g8 + 2 * p]);
    }
    const float2 h2v = *reinterpret_cast<const float2*>(&h2[y0]);
    const float  Az  = A[z];
    const float  h1z = h1[z];

    const float* Xb = X   + (size_t)bg * T_LEN * DX;
    float*       Ob = out + (size_t)bg * T_LEN * DX;

    // ---- z0: first dx dims forced with alpha=1, rest zero ----
    float zcur = 0.0f, x_next = 0.0f;
    if (z < DX) {
        float x0 = Xb[z];
        zcur   = (x0 != x0) ? 0.0f : x0;     // NaN -> keep 0
        x_next = x0;                          // step-0 forcing reuses X[:,0]
    }

    for (int step = 0; step < T_LEN; ++step) {
        // ---- phase 0: teacher forcing, publish zf ----
        float zf;
        if (z < DX) {
            float x = x_next;
            zf = (x != x) ? zcur : fmaf(ALPHA, x, (1.0f - ALPHA) * zcur);
        } else {
            zf = zcur;
        }
        szfB[b][zsl] = zf;
        if (z < DX && step + 1 < T_LEN)
            x_next = Xb[(size_t)(step + 1) * DX + z];   // prefetch for next iter
        __syncthreads();                                 // B1: zf ready

        // ---- GEMM1 (k-split): partial[y0/y1][bb] over this thread's 32 k ----
        float2 a0[BB], a1[BB];
#pragma unroll
        for (int bb = 0; bb < BB; ++bb) { a0[bb] = make_float2(0.f, 0.f);
                                          a1[bb] = make_float2(0.f, 0.f); }
#pragma unroll
        for (int j = 0; j < 8; ++j) {
#pragma unroll
            for (int bb = 0; bb < BB; ++bb) {
                float4 v = *reinterpret_cast<const float4*>(&szfB[bb][kb + 4 * j]);
                float2 lo = make_float2(v.x, v.y), hi = make_float2(v.z, v.w);
                a0[bb] = ffma2(w2a[2 * j],     lo, a0[bb]);
                a0[bb] = ffma2(w2a[2 * j + 1], hi, a0[bb]);
                a1[bb] = ffma2(w2b[2 * j],     lo, a1[bb]);
                a1[bb] = ffma2(w2b[2 * j + 1], hi, a1[bb]);
            }
        }
        // combine k-halves with partner lane (lane^1), relu, store 2 batches each
        {
            float s0[BB], s1[BB];
#pragma unroll
            for (int bb = 0; bb < BB; ++bb) {
                s0[bb] = a0[bb].x + a0[bb].y;
                s1[bb] = a1[bb].x + a1[bb].y;
                s0[bb] += __shfl_xor_sync(0xffffffffu, s0[bb], 1);
                s1[bb] += __shfl_xor_sync(0xffffffffu, s1[bb], 1);
            }
            // kh==0 stores batches 0,1; kh==1 stores batches 2,3
            int bs = kh * 2;
#pragma unroll
            for (int u = 0; u < 2; ++u) {
                int bb = bs + u;
                float2 hv;
                hv.x = fmaxf(s0[bb] + h2v.x, 0.0f);
                hv.y = fmaxf(s1[bb] + h2v.y, 0.0f);
                *reinterpret_cast<float2*>(&shB[bb][y0]) = hv;
            }
        }
        __syncthreads();                                 // B2: hidden ready

        // ---- GEMM2: part[g8][b][z] = W1[z, 32g8:+32] . hidden[32g8:+32, b] ----
        float2 c0[BB], c1[BB];
#pragma unroll
        for (int bb = 0; bb < BB; ++bb) { c0[bb] = make_float2(0.f, 0.f);
                                          c1[bb] = make_float2(0.f, 0.f); }
#pragma unroll
        for (int yq = 0; yq < 8; ++yq) {
#pragma unroll
            for (int bb = 0; bb < BB; ++bb) {
                float4 hv = *reinterpret_cast<const float4*>(&shB[bb][32 * g8 + 4 * yq]);
                float2 lo = make_float2(hv.x, hv.y), hi = make_float2(hv.z, hv.w);
                c0[bb] = ffma2(w1a[2 * yq],     lo, c0[bb]);
                c0[bb] = ffma2(w1a[2 * yq + 1], hi, c0[bb]);
                c1[bb] = ffma2(w1b[2 * yq],     lo, c1[bb]);
                c1[bb] = ffma2(w1b[2 * yq + 1], hi, c1[bb]);
            }
        }
#pragma unroll
        for (int bb = 0; bb < BB; ++bb) {
            float2 pr;
            pr.x = c0[bb].x + c0[bb].y;                  // z = zg0
            pr.y = c1[bb].x + c1[bb].y;                  // z = zg0+1
            *reinterpret_cast<float2*>(&sPart[g8][bb][zg0]) = pr;
        }
        __syncthreads();                                 // B3: partials ready

        // ---- reduce 8 groups + state update + output ----
        float s = 0.0f;
#pragma unroll
        for (int g = 0; g < 8; ++g) s += sPart[g][b][z];
        float znew = fmaf(Az, zf, s + h1z);
        zcur = znew;
        if (z < DX)
            Ob[(size_t)step * DX + z] = znew;            // coalesced
    }
}

extern "C" void kernel_launch(void* const* d_in, const int* in_sizes, int n_in,
                              void* d_out, int out_size)
{
    const float* X  = (const float*)d_in[0];   // (512, 1024, 32)
    const float* A  = (const float*)d_in[1];   // (64,)
    const float* W1 = (const float*)d_in[2];   // (64, 256)
    const float* W2 = (const float*)d_in[3];   // (256, 64)
    const float* h1 = (const float*)d_in[4];   // (64,)
    const float* h2 = (const float*)d_in[5];   // (256,)
    plrnn_kernel<<<NCTA, NTHR>>>(X, A, W1, W2, h1, h2, (float*)d_out);
}